// round 15
// baseline (speedup 1.0000x reference)
#include <cuda_runtime.h>
#include <cuda_fp16.h>
#include <math.h>

#define NCELLS   (512 * 512)
#define M_LEN    262144
#define NCOILS   16
#define NJ       6
#define CENTER   3072
#define TBL_LEN  6145
#define NBATCH   2
#define WPB      4               // warps per block
#define PPB      16              // points per block (4 per warp)

#define HROWS    517             // 512 + 5 halo
#define HSTRIDE  520             // padded row stride in cells (even!)
#define ROW_U4   (HSTRIDE * 4)   // row stride in uint4 units

// Grid copies merged in ONE array (single base address in the kernel):
//   [0,   CSZ)  copy A: cell c at slot c      (even col0 points)
//   [CSZ, 2CSZ) copy B: cell c at slot c + 1  (odd  col0 points)
// => the 6-cell row window always starts at a 128B-aligned slot.
#define CSZ ((size_t)NBATCH * HROWS * HSTRIDE * NCOILS)
__device__ __align__(256) __half2 g_xT[2 * CSZ + NCOILS];

// ---------------------------------------------------------------------------
// Transpose + fp16 + halo: x[b][coil][ri][cell] -> both alignment copies.
// x is read streaming (__ldcs) so it doesn't displace the grid in L2.
// ---------------------------------------------------------------------------
__global__ void transpose_kernel(const float* __restrict__ x) {
    int idx = blockIdx.x * blockDim.x + threadIdx.x;
    if (idx >= NBATCH * HROWS * HROWS) return;
    int b   = idx / (HROWS * HROWS);
    int rem = idx - b * (HROWS * HROWS);
    int r   = rem / HROWS;
    int c   = rem - r * HROWS;
    int cell = ((r & 511) << 9) | (c & 511);

    const float* xb = x + (size_t)b * NCOILS * 2 * NCELLS + cell;
    __half2 v[NCOILS];
#pragma unroll
    for (int cc = 0; cc < NCOILS; cc++) {
        float re = __ldcs(xb + (size_t)(cc * 2 + 0) * NCELLS);
        float im = __ldcs(xb + (size_t)(cc * 2 + 1) * NCELLS);
        v[cc] = __floats2half2_rn(re, im);
    }
    const size_t slot = ((size_t)(b * HROWS + r) * HSTRIDE + c) * NCOILS;
    uint4* dstA = reinterpret_cast<uint4*>(g_xT + slot);
    uint4* dstB = reinterpret_cast<uint4*>(g_xT + CSZ + slot + NCOILS);
#pragma unroll
    for (int i = 0; i < 4; i++) dstA[i] = reinterpret_cast<uint4*>(v)[i];
#pragma unroll
    for (int i = 0; i < 4; i++) dstB[i] = reinterpret_cast<uint4*>(v)[i];
}

// ---------------------------------------------------------------------------
// Interp: 128 thr = 4 warps; 4 points per warp (8 lanes each).
// Lane: pt = l>>3, ks = (l>>2)&1, cc = l&3 (coil quad via LDG.128).
// Parity-selected copy offset keeps every 128B slice line-aligned.
// S-trick: S = r1 + swap(r2); G1 += c0r*S, G2 += c0i*S;
// ar = G1.x - G2.y, ai = G1.y + G2.x after ks-reduction.
// Batch 1 processed first (L2-hot); output stored with __stcs.
// ---------------------------------------------------------------------------
__global__ __launch_bounds__(128, 11) void interp_kernel(
    const float* __restrict__ om,
    const float* __restrict__ t0,
    const float* __restrict__ t1,
    float* __restrict__ out)
{
    __shared__ uint2  s_c0[WPB][4][NJ];   // {h2(c0r,c0r), h2(c0i,c0i)}
    __shared__ uint2  s_c1[WPB][4][NJ];   // {h2(c1r,c1r), h2(c1i,-c1i)}
    __shared__ float2 s_ph[WPB][4];
    __shared__ float  s_out[32][PPB + 1];

    const int tid  = threadIdx.x;
    const int w    = tid >> 5;
    const int lane = tid & 31;
    const int pt   = lane >> 3;
    const int g    = lane & 7;
    const unsigned FULL = 0xffffffffu;

    const int gbase = blockIdx.x * PPB;
    const int b_blk = 1 - (gbase >> 18);           // batch 1 first (L2-hot)
    const int m0    = gbase & (M_LEN - 1);
    const int m     = m0 + w * 4 + pt;

    const float om0 = __ldg(&om[(size_t)(b_blk * 2 + 0) * M_LEN + m]);
    const float om1 = __ldg(&om[(size_t)(b_blk * 2 + 1) * M_LEN + m]);
    const float SCALE = 512.0f / (2.0f * 3.14159265358979323846f);
    const float tm0 = om0 * SCALE;
    const float tm1 = om1 * SCALE;
    const float k0f = 1.0f + floorf(tm0 - 3.0f);
    const float k1f = 1.0f + floorf(tm1 - 3.0f);
    const int gi0 = (int)k0f;
    const int gi1 = (int)k1f;

#pragma unroll
    for (int it = 0; it < 2; it++) {
        const int item = g + it * 8;
        if (item < 6) {
            const int j = item;
            int d0 = __float2int_rn((tm0 - (k0f + (float)j)) * 1024.0f) + CENTER;
            float c0r = __ldg(&t0[d0]);
            float c0i = __ldg(&t0[TBL_LEN + d0]);
            __half2 R = __floats2half2_rn(c0r, c0r);
            __half2 I = __floats2half2_rn(c0i, c0i);
            s_c0[w][pt][j] = make_uint2(*(unsigned*)&R, *(unsigned*)&I);
        } else if (item < 12) {
            const int j = item - 6;
            int d1 = __float2int_rn((tm1 - (k1f + (float)j)) * 1024.0f) + CENTER;
            float c1r = __ldg(&t1[d1]);
            float c1i = __ldg(&t1[TBL_LEN + d1]);
            __half2 A  = __floats2half2_rn(c1r, c1r);
            __half2 Bp = __floats2half2_rn(c1i, -c1i);
            s_c1[w][pt][j] = make_uint2(*(unsigned*)&A, *(unsigned*)&Bp);
        } else if (item == 12) {
            float ph = om0 * 128.0f + om1 * 128.0f;
            float sp, cp;
            sincosf(ph, &sp, &cp);
            s_ph[w][pt] = make_float2(cp, sp);
        }
    }
    __syncwarp(FULL);

    const int cc = lane & 3;
    const int ks = (lane >> 2) & 1;

    const uint2 q0 = s_c1[w][pt][ks];
    const uint2 q1 = s_c1[w][pt][2 + ks];
    const uint2 q2 = s_c1[w][pt][4 + ks];
    const __half2 A0 = *(__half2*)&q0.x, B0 = *(__half2*)&q0.y;
    const __half2 A1 = *(__half2*)&q1.x, B1 = *(__half2*)&q1.y;
    const __half2 A2 = *(__half2*)&q2.x, B2 = *(__half2*)&q2.y;

    const int row0 = gi0 & 511;
    const int col0 = gi1 & 511;
    const int p    = col0 & 1;                       // alignment parity
    const size_t poff = p ? (CSZ + NCOILS) : 0;      // copy select (one base)
    const uint4* base = reinterpret_cast<const uint4*>(g_xT + poff)
        + ((size_t)(b_blk * HROWS + row0) * HSTRIDE + col0 + ks) * 4 + cc;

    const __half2 hz = __floats2half2_rn(0.f, 0.f);
    __half2 G1[4], G2[4];
#pragma unroll
    for (int c = 0; c < 4; c++) { G1[c] = hz; G2[c] = hz; }

#pragma unroll
    for (int j0 = 0; j0 < NJ; j0++) {
        const uint4* rp = base + j0 * ROW_U4;
        const uint4 d0 = __ldg(rp);
        const uint4 d1 = __ldg(rp + 8);    // +2 cells
        const uint4 d2 = __ldg(rp + 16);   // +4 cells
        const __half2* e0 = reinterpret_cast<const __half2*>(&d0);
        const __half2* e1 = reinterpret_cast<const __half2*>(&d1);
        const __half2* e2 = reinterpret_cast<const __half2*>(&d2);

        const uint2 c0p = s_c0[w][pt][j0];
        const __half2 C0R = *(const __half2*)&c0p.x;
        const __half2 C0I = *(const __half2*)&c0p.y;

#pragma unroll
        for (int c = 0; c < 4; c++) {
            __half2 r1 = __hmul2(A0, e0[c]);
            r1 = __hfma2(A1, e1[c], r1);
            r1 = __hfma2(A2, e2[c], r1);
            __half2 r2 = __hmul2(B0, e0[c]);
            r2 = __hfma2(B1, e1[c], r2);
            r2 = __hfma2(B2, e2[c], r2);
            const __half2 S = __hadd2(r1, __lowhigh2highlow(r2));
            G1[c] = __hfma2(C0R, S, G1[c]);
            G2[c] = __hfma2(C0I, S, G2[c]);
        }
    }

    // reduce the two cell slots (lane xor 4) in half2
#pragma unroll
    for (int c = 0; c < 4; c++) {
        unsigned u;
        u = __shfl_xor_sync(FULL, *(unsigned*)&G1[c], 4);
        G1[c] = __hadd2(G1[c], *(__half2*)&u);
        u = __shfl_xor_sync(FULL, *(unsigned*)&G2[c], 4);
        G2[c] = __hadd2(G2[c], *(__half2*)&u);
    }

    if (ks == 0) {
        const float2 ph = s_ph[w][pt];
        const int pp = w * 4 + pt;
#pragma unroll
        for (int c = 0; c < 4; c++) {
            const float2 g1 = __half22float2(G1[c]);
            const float2 g2 = __half22float2(G2[c]);
            const float ar = g1.x - g2.y;
            const float ai = g1.y + g2.x;
            const int coil = cc * 4 + c;
            s_out[coil * 2 + 0][pp] = ar * ph.x - ai * ph.y;
            s_out[coil * 2 + 1][pp] = ar * ph.y + ai * ph.x;
        }
    }
    __syncthreads();

    // out[b][coil][ri][m0+pp]: 32 rows x 16 consecutive m (64B runs),
    // streaming stores (output is never re-read).
#pragma unroll
    for (int i = tid; i < 32 * PPB; i += 128) {
        const int pp = i & (PPB - 1);
        const int r  = i >> 4;
        __stcs(&out[((size_t)(b_blk * NCOILS * 2) + r) * M_LEN + m0 + pp],
               s_out[r][pp]);
    }
}

extern "C" void kernel_launch(void* const* d_in, const int* in_sizes, int n_in,
                              void* d_out, int out_size) {
    const float* x  = (const float*)d_in[0];   // (2,16,2,512,512)
    const float* om = (const float*)d_in[1];   // (2,2,262144)
    const float* t0 = (const float*)d_in[2];   // (2,6145)
    const float* t1 = (const float*)d_in[3];   // (2,6145)
    float* out = (float*)d_out;                // (2,16,2,262144)

    int ncells_h = NBATCH * HROWS * HROWS;
    transpose_kernel<<<(ncells_h + 255) / 256, 256>>>(x);
    interp_kernel<<<(NBATCH * M_LEN) / PPB, 128>>>(om, t0, t1, out);
}

// round 16
// speedup vs baseline: 1.0812x; 1.0812x over previous
#include <cuda_runtime.h>
#include <cuda_fp16.h>
#include <math.h>

#define NCELLS   (512 * 512)
#define M_LEN    262144
#define NCOILS   16
#define NJ       6
#define CENTER   3072
#define TBL_LEN  6145
#define NBATCH   2
#define WPB      8               // warps per block
#define PPB      32              // points per block (4 per warp)

#define HROWS    517             // 512 + 5 halo
#define HSTRIDE  520             // padded row stride in cells (even!)
#define ROW_U4   (HSTRIDE * 4)   // row stride in uint4 units

// Two alignment copies of the halo-padded fp16 grid (64B per cell):
//   copy A: cell c at slot c        (even col0 points read here)
//   copy B: cell c at slot c + 1    (odd  col0 points read here)
// => the 6-cell row window always starts at a 128B-aligned slot.
__device__ __align__(256) __half2 g_xTa[(size_t)NBATCH * HROWS * HSTRIDE * NCOILS];
__device__ __align__(256) __half2 g_xTb[(size_t)NBATCH * HROWS * HSTRIDE * NCOILS];

// ---------------------------------------------------------------------------
// Transpose + fp16 + halo: x[b][coil][ri][cell] -> both alignment copies.
// x is read streaming (__ldcs) so it doesn't displace the grid in L2.
// ---------------------------------------------------------------------------
__global__ void transpose_kernel(const float* __restrict__ x) {
    int idx = blockIdx.x * blockDim.x + threadIdx.x;
    if (idx >= NBATCH * HROWS * HROWS) return;
    int b   = idx / (HROWS * HROWS);
    int rem = idx - b * (HROWS * HROWS);
    int r   = rem / HROWS;
    int c   = rem - r * HROWS;
    int cell = ((r & 511) << 9) | (c & 511);

    const float* xb = x + (size_t)b * NCOILS * 2 * NCELLS + cell;
    __half2 v[NCOILS];
#pragma unroll
    for (int cc = 0; cc < NCOILS; cc++) {
        float re = __ldcs(xb + (size_t)(cc * 2 + 0) * NCELLS);
        float im = __ldcs(xb + (size_t)(cc * 2 + 1) * NCELLS);
        v[cc] = __floats2half2_rn(re, im);
    }
    const size_t slot = ((size_t)(b * HROWS + r) * HSTRIDE + c) * NCOILS;
    uint4* dstA = reinterpret_cast<uint4*>(g_xTa + slot);
    uint4* dstB = reinterpret_cast<uint4*>(g_xTb + slot + NCOILS);  // c -> c+1
#pragma unroll
    for (int i = 0; i < 4; i++) dstA[i] = reinterpret_cast<uint4*>(v)[i];
#pragma unroll
    for (int i = 0; i < 4; i++) dstB[i] = reinterpret_cast<uint4*>(v)[i];
}

// ---------------------------------------------------------------------------
// Interp: 256 thr = 8 warps; 4 points per warp (8 lanes each).
// Lane: pt = l>>3, ks = (l>>2)&1, cc = l&3 (coil quad via LDG.128).
// Parity-selected grid copy makes every 128B slice line-aligned.
// S-trick: S = r1 + swap(r2); G1 += c0r*S, G2 += c0i*S;
// ar = G1.x - G2.y, ai = G1.y + G2.x after ks-reduction.
// Batch 1 is processed FIRST (its grid copy is hottest in L2 after the
// transpose); output stored with __stcs (never re-read).
// ---------------------------------------------------------------------------
__global__ __launch_bounds__(256, 5) void interp_kernel(
    const float* __restrict__ om,
    const float* __restrict__ t0,
    const float* __restrict__ t1,
    float* __restrict__ out)
{
    __shared__ uint2  s_c0[WPB][4][NJ];   // {h2(c0r,c0r), h2(c0i,c0i)}
    __shared__ uint2  s_c1[WPB][4][NJ];   // {h2(c1r,c1r), h2(c1i,-c1i)}
    __shared__ float2 s_ph[WPB][4];
    __shared__ float  s_out[32][PPB + 1];

    const int tid  = threadIdx.x;
    const int w    = tid >> 5;
    const int lane = tid & 31;
    const int pt   = lane >> 3;
    const int g    = lane & 7;
    const unsigned FULL = 0xffffffffu;

    const int gbase = blockIdx.x * PPB;
    const int b_blk = 1 - (gbase >> 18);           // batch 1 first (L2-hot)
    const int m0    = gbase & (M_LEN - 1);
    const int m     = m0 + w * 4 + pt;

    const float om0 = __ldg(&om[(size_t)(b_blk * 2 + 0) * M_LEN + m]);
    const float om1 = __ldg(&om[(size_t)(b_blk * 2 + 1) * M_LEN + m]);
    const float SCALE = 512.0f / (2.0f * 3.14159265358979323846f);
    const float tm0 = om0 * SCALE;
    const float tm1 = om1 * SCALE;
    const float k0f = 1.0f + floorf(tm0 - 3.0f);
    const float k1f = 1.0f + floorf(tm1 - 3.0f);
    const int gi0 = (int)k0f;
    const int gi1 = (int)k1f;

#pragma unroll
    for (int it = 0; it < 2; it++) {
        const int item = g + it * 8;
        if (item < 6) {
            const int j = item;
            int d0 = __float2int_rn((tm0 - (k0f + (float)j)) * 1024.0f) + CENTER;
            float c0r = __ldg(&t0[d0]);
            float c0i = __ldg(&t0[TBL_LEN + d0]);
            __half2 R = __floats2half2_rn(c0r, c0r);
            __half2 I = __floats2half2_rn(c0i, c0i);
            s_c0[w][pt][j] = make_uint2(*(unsigned*)&R, *(unsigned*)&I);
        } else if (item < 12) {
            const int j = item - 6;
            int d1 = __float2int_rn((tm1 - (k1f + (float)j)) * 1024.0f) + CENTER;
            float c1r = __ldg(&t1[d1]);
            float c1i = __ldg(&t1[TBL_LEN + d1]);
            __half2 A  = __floats2half2_rn(c1r, c1r);
            __half2 Bp = __floats2half2_rn(c1i, -c1i);
            s_c1[w][pt][j] = make_uint2(*(unsigned*)&A, *(unsigned*)&Bp);
        } else if (item == 12) {
            float ph = om0 * 128.0f + om1 * 128.0f;
            float sp, cp;
            __sincosf(ph, &sp, &cp);   // fast-path: |ph|<=256pi, err ~2e-5 rad
            s_ph[w][pt] = make_float2(cp, sp);
        }
    }
    __syncwarp(FULL);

    const int cc = lane & 3;
    const int ks = (lane >> 2) & 1;

    const uint2 q0 = s_c1[w][pt][ks];
    const uint2 q1 = s_c1[w][pt][2 + ks];
    const uint2 q2 = s_c1[w][pt][4 + ks];
    const __half2 A0 = *(__half2*)&q0.x, B0 = *(__half2*)&q0.y;
    const __half2 A1 = *(__half2*)&q1.x, B1 = *(__half2*)&q1.y;
    const __half2 A2 = *(__half2*)&q2.x, B2 = *(__half2*)&q2.y;

    const int row0 = gi0 & 511;
    const int col0 = gi1 & 511;
    const int p    = col0 & 1;                       // alignment parity
    const __half2* gsel = p ? g_xTb : g_xTa;
    const uint4* base = reinterpret_cast<const uint4*>(gsel)
        + ((size_t)(b_blk * HROWS + row0) * HSTRIDE + col0 + p + ks) * 4 + cc;

    const __half2 hz = __floats2half2_rn(0.f, 0.f);
    __half2 G1[4], G2[4];
#pragma unroll
    for (int c = 0; c < 4; c++) { G1[c] = hz; G2[c] = hz; }

#pragma unroll
    for (int j0 = 0; j0 < NJ; j0++) {
        const uint4* rp = base + j0 * ROW_U4;
        const uint4 d0 = __ldg(rp);
        const uint4 d1 = __ldg(rp + 8);    // +2 cells
        const uint4 d2 = __ldg(rp + 16);   // +4 cells
        const __half2* e0 = reinterpret_cast<const __half2*>(&d0);
        const __half2* e1 = reinterpret_cast<const __half2*>(&d1);
        const __half2* e2 = reinterpret_cast<const __half2*>(&d2);

        const uint2 c0p = s_c0[w][pt][j0];
        const __half2 C0R = *(const __half2*)&c0p.x;
        const __half2 C0I = *(const __half2*)&c0p.y;

#pragma unroll
        for (int c = 0; c < 4; c++) {
            __half2 r1 = __hmul2(A0, e0[c]);
            r1 = __hfma2(A1, e1[c], r1);
            r1 = __hfma2(A2, e2[c], r1);
            __half2 r2 = __hmul2(B0, e0[c]);
            r2 = __hfma2(B1, e1[c], r2);
            r2 = __hfma2(B2, e2[c], r2);
            const __half2 S = __hadd2(r1, __lowhigh2highlow(r2));
            G1[c] = __hfma2(C0R, S, G1[c]);
            G2[c] = __hfma2(C0I, S, G2[c]);
        }
    }

    // reduce the two cell slots (lane xor 4) in half2
#pragma unroll
    for (int c = 0; c < 4; c++) {
        unsigned u;
        u = __shfl_xor_sync(FULL, *(unsigned*)&G1[c], 4);
        G1[c] = __hadd2(G1[c], *(__half2*)&u);
        u = __shfl_xor_sync(FULL, *(unsigned*)&G2[c], 4);
        G2[c] = __hadd2(G2[c], *(__half2*)&u);
    }

    if (ks == 0) {
        const float2 ph = s_ph[w][pt];
        const int pp = w * 4 + pt;
#pragma unroll
        for (int c = 0; c < 4; c++) {
            const float2 g1 = __half22float2(G1[c]);
            const float2 g2 = __half22float2(G2[c]);
            const float ar = g1.x - g2.y;
            const float ai = g1.y + g2.x;
            const int coil = cc * 4 + c;
            s_out[coil * 2 + 0][pp] = ar * ph.x - ai * ph.y;
            s_out[coil * 2 + 1][pp] = ar * ph.y + ai * ph.x;
        }
    }
    __syncthreads();

    // out[b][coil][ri][m0+pp]: 32 rows x 32 consecutive m (128B runs),
    // streaming stores (output is never re-read).
#pragma unroll
    for (int i = tid; i < 32 * PPB; i += 256) {
        const int pp = i & (PPB - 1);
        const int r  = i >> 5;
        __stcs(&out[((size_t)(b_blk * NCOILS * 2) + r) * M_LEN + m0 + pp],
               s_out[r][pp]);
    }
}

extern "C" void kernel_launch(void* const* d_in, const int* in_sizes, int n_in,
                              void* d_out, int out_size) {
    const float* x  = (const float*)d_in[0];   // (2,16,2,512,512)
    const float* om = (const float*)d_in[1];   // (2,2,262144)
    const float* t0 = (const float*)d_in[2];   // (2,6145)
    const float* t1 = (const float*)d_in[3];   // (2,6145)
    float* out = (float*)d_out;                // (2,16,2,262144)

    int ncells_h = NBATCH * HROWS * HROWS;
    transpose_kernel<<<(ncells_h + 255) / 256, 256>>>(x);
    interp_kernel<<<(NBATCH * M_LEN) / PPB, 256>>>(om, t0, t1, out);
}

// round 17
// speedup vs baseline: 1.0911x; 1.0092x over previous
#include <cuda_runtime.h>
#include <cuda_fp16.h>
#include <math.h>

#define NCELLS   (512 * 512)
#define M_LEN    262144
#define NCOILS   16
#define NJ       6
#define CENTER   3072
#define TBL_LEN  6145
#define NBATCH   2
#define WPB      8               // warps per block
#define PPB      32              // points per block (4 per warp)

#define HROWS    517             // 512 + 5 halo
#define HSTRIDE  520             // padded row stride in cells (even!)
#define ROW_U4   (HSTRIDE * 4)   // row stride in uint4 units

// Two alignment copies of the halo-padded fp16 grid (64B per cell):
//   copy A: cell c at slot c        (even col0 points read here)
//   copy B: cell c at slot c + 1    (odd  col0 points read here)
// => the 6-cell row window always starts at a 128B-aligned slot.
__device__ __align__(256) __half2 g_xTa[(size_t)NBATCH * HROWS * HSTRIDE * NCOILS];
__device__ __align__(256) __half2 g_xTb[(size_t)NBATCH * HROWS * HSTRIDE * NCOILS];

// ---------------------------------------------------------------------------
// Transpose + fp16 + halo: x[b][coil][ri][cell] -> both alignment copies.
// x is read streaming (__ldcs); signals PDL completion after its stores.
// ---------------------------------------------------------------------------
__global__ void transpose_kernel(const float* __restrict__ x) {
    int idx = blockIdx.x * blockDim.x + threadIdx.x;
    if (idx < NBATCH * HROWS * HROWS) {
        int b   = idx / (HROWS * HROWS);
        int rem = idx - b * (HROWS * HROWS);
        int r   = rem / HROWS;
        int c   = rem - r * HROWS;
        int cell = ((r & 511) << 9) | (c & 511);

        const float* xb = x + (size_t)b * NCOILS * 2 * NCELLS + cell;
        __half2 v[NCOILS];
#pragma unroll
        for (int cc = 0; cc < NCOILS; cc++) {
            float re = __ldcs(xb + (size_t)(cc * 2 + 0) * NCELLS);
            float im = __ldcs(xb + (size_t)(cc * 2 + 1) * NCELLS);
            v[cc] = __floats2half2_rn(re, im);
        }
        const size_t slot = ((size_t)(b * HROWS + r) * HSTRIDE + c) * NCOILS;
        uint4* dstA = reinterpret_cast<uint4*>(g_xTa + slot);
        uint4* dstB = reinterpret_cast<uint4*>(g_xTb + slot + NCOILS);  // c->c+1
#pragma unroll
        for (int i = 0; i < 4; i++) dstA[i] = reinterpret_cast<uint4*>(v)[i];
#pragma unroll
        for (int i = 0; i < 4; i++) dstB[i] = reinterpret_cast<uint4*>(v)[i];
    }
    cudaTriggerProgrammaticLaunchCompletion();
}

// ---------------------------------------------------------------------------
// Interp: 256 thr = 8 warps; 4 points per warp (8 lanes each).
// Lane: pt = l>>3, ks = (l>>2)&1, cc = l&3 (coil quad via LDG.128).
// PDL: setup (om/tables/phase, transpose-independent) runs overlapped with
// the transpose tail; cudaGridDependencySynchronize() before grid reads.
// Parity-selected grid copy makes every 128B slice line-aligned.
// S-trick: S = r1 + swap(r2); G1 += c0r*S, G2 += c0i*S;
// ar = G1.x - G2.y, ai = G1.y + G2.x after ks-reduction.
// Batch 1 first (L2-hot); output stored with __stcs.
// ---------------------------------------------------------------------------
__global__ __launch_bounds__(256, 5) void interp_kernel(
    const float* __restrict__ om,
    const float* __restrict__ t0,
    const float* __restrict__ t1,
    float* __restrict__ out)
{
    __shared__ uint2  s_c0[WPB][4][NJ];   // {h2(c0r,c0r), h2(c0i,c0i)}
    __shared__ uint2  s_c1[WPB][4][NJ];   // {h2(c1r,c1r), h2(c1i,-c1i)}
    __shared__ float2 s_ph[WPB][4];
    __shared__ float  s_out[32][PPB + 1];

    const int tid  = threadIdx.x;
    const int w    = tid >> 5;
    const int lane = tid & 31;
    const int pt   = lane >> 3;
    const int g    = lane & 7;
    const unsigned FULL = 0xffffffffu;

    const int gbase = blockIdx.x * PPB;
    const int b_blk = 1 - (gbase >> 18);           // batch 1 first (L2-hot)
    const int m0    = gbase & (M_LEN - 1);
    const int m     = m0 + w * 4 + pt;

    const float om0 = __ldg(&om[(size_t)(b_blk * 2 + 0) * M_LEN + m]);
    const float om1 = __ldg(&om[(size_t)(b_blk * 2 + 1) * M_LEN + m]);
    const float SCALE = 512.0f / (2.0f * 3.14159265358979323846f);
    const float tm0 = om0 * SCALE;
    const float tm1 = om1 * SCALE;
    const float k0f = 1.0f + floorf(tm0 - 3.0f);
    const float k1f = 1.0f + floorf(tm1 - 3.0f);
    const int gi0 = (int)k0f;
    const int gi1 = (int)k1f;

#pragma unroll
    for (int it = 0; it < 2; it++) {
        const int item = g + it * 8;
        if (item < 6) {
            const int j = item;
            int d0 = __float2int_rn((tm0 - (k0f + (float)j)) * 1024.0f) + CENTER;
            float c0r = __ldg(&t0[d0]);
            float c0i = __ldg(&t0[TBL_LEN + d0]);
            __half2 R = __floats2half2_rn(c0r, c0r);
            __half2 I = __floats2half2_rn(c0i, c0i);
            s_c0[w][pt][j] = make_uint2(*(unsigned*)&R, *(unsigned*)&I);
        } else if (item < 12) {
            const int j = item - 6;
            int d1 = __float2int_rn((tm1 - (k1f + (float)j)) * 1024.0f) + CENTER;
            float c1r = __ldg(&t1[d1]);
            float c1i = __ldg(&t1[TBL_LEN + d1]);
            __half2 A  = __floats2half2_rn(c1r, c1r);
            __half2 Bp = __floats2half2_rn(c1i, -c1i);
            s_c1[w][pt][j] = make_uint2(*(unsigned*)&A, *(unsigned*)&Bp);
        } else if (item == 12) {
            float ph = om0 * 128.0f + om1 * 128.0f;
            float sp, cp;
            __sincosf(ph, &sp, &cp);   // fast-path: |ph|<=256pi, err ~2e-5 rad
            s_ph[w][pt] = make_float2(cp, sp);
        }
    }
    __syncwarp(FULL);

    const int cc = lane & 3;
    const int ks = (lane >> 2) & 1;

    const uint2 q0 = s_c1[w][pt][ks];
    const uint2 q1 = s_c1[w][pt][2 + ks];
    const uint2 q2 = s_c1[w][pt][4 + ks];
    const __half2 A0 = *(__half2*)&q0.x, B0 = *(__half2*)&q0.y;
    const __half2 A1 = *(__half2*)&q1.x, B1 = *(__half2*)&q1.y;
    const __half2 A2 = *(__half2*)&q2.x, B2 = *(__half2*)&q2.y;

    const int row0 = gi0 & 511;
    const int col0 = gi1 & 511;
    const int p    = col0 & 1;                       // alignment parity
    const __half2* gsel = p ? g_xTb : g_xTa;
    const uint4* base = reinterpret_cast<const uint4*>(gsel)
        + ((size_t)(b_blk * HROWS + row0) * HSTRIDE + col0 + p + ks) * 4 + cc;

    // wait for the transpose grid to be visible (PDL dependency)
    cudaGridDependencySynchronize();

    const __half2 hz = __floats2half2_rn(0.f, 0.f);
    __half2 G1[4], G2[4];
#pragma unroll
    for (int c = 0; c < 4; c++) { G1[c] = hz; G2[c] = hz; }

#pragma unroll
    for (int j0 = 0; j0 < NJ; j0++) {
        const uint4* rp = base + j0 * ROW_U4;
        const uint4 d0 = __ldg(rp);
        const uint4 d1 = __ldg(rp + 8);    // +2 cells
        const uint4 d2 = __ldg(rp + 16);   // +4 cells
        const __half2* e0 = reinterpret_cast<const __half2*>(&d0);
        const __half2* e1 = reinterpret_cast<const __half2*>(&d1);
        const __half2* e2 = reinterpret_cast<const __half2*>(&d2);

        const uint2 c0p = s_c0[w][pt][j0];
        const __half2 C0R = *(const __half2*)&c0p.x;
        const __half2 C0I = *(const __half2*)&c0p.y;

#pragma unroll
        for (int c = 0; c < 4; c++) {
            __half2 r1 = __hmul2(A0, e0[c]);
            r1 = __hfma2(A1, e1[c], r1);
            r1 = __hfma2(A2, e2[c], r1);
            __half2 r2 = __hmul2(B0, e0[c]);
            r2 = __hfma2(B1, e1[c], r2);
            r2 = __hfma2(B2, e2[c], r2);
            const __half2 S = __hadd2(r1, __lowhigh2highlow(r2));
            G1[c] = __hfma2(C0R, S, G1[c]);
            G2[c] = __hfma2(C0I, S, G2[c]);
        }
    }

    // reduce the two cell slots (lane xor 4) in half2
#pragma unroll
    for (int c = 0; c < 4; c++) {
        unsigned u;
        u = __shfl_xor_sync(FULL, *(unsigned*)&G1[c], 4);
        G1[c] = __hadd2(G1[c], *(__half2*)&u);
        u = __shfl_xor_sync(FULL, *(unsigned*)&G2[c], 4);
        G2[c] = __hadd2(G2[c], *(__half2*)&u);
    }

    if (ks == 0) {
        const float2 ph = s_ph[w][pt];
        const int pp = w * 4 + pt;
#pragma unroll
        for (int c = 0; c < 4; c++) {
            const float2 g1 = __half22float2(G1[c]);
            const float2 g2 = __half22float2(G2[c]);
            const float ar = g1.x - g2.y;
            const float ai = g1.y + g2.x;
            const int coil = cc * 4 + c;
            s_out[coil * 2 + 0][pp] = ar * ph.x - ai * ph.y;
            s_out[coil * 2 + 1][pp] = ar * ph.y + ai * ph.x;
        }
    }
    __syncthreads();

    // out[b][coil][ri][m0+pp]: 32 rows x 32 consecutive m (128B runs),
    // streaming stores (output is never re-read).
#pragma unroll
    for (int i = tid; i < 32 * PPB; i += 256) {
        const int pp = i & (PPB - 1);
        const int r  = i >> 5;
        __stcs(&out[((size_t)(b_blk * NCOILS * 2) + r) * M_LEN + m0 + pp],
               s_out[r][pp]);
    }
}

extern "C" void kernel_launch(void* const* d_in, const int* in_sizes, int n_in,
                              void* d_out, int out_size) {
    const float* x  = (const float*)d_in[0];   // (2,16,2,512,512)
    const float* om = (const float*)d_in[1];   // (2,2,262144)
    const float* t0 = (const float*)d_in[2];   // (2,6145)
    const float* t1 = (const float*)d_in[3];   // (2,6145)
    float* out = (float*)d_out;                // (2,16,2,262144)

    int ncells_h = NBATCH * HROWS * HROWS;
    transpose_kernel<<<(ncells_h + 255) / 256, 256>>>(x);

    // Interp launched with programmatic stream serialization: its setup
    // phase overlaps the transpose tail; the grid reads are guarded by
    // cudaGridDependencySynchronize() inside the kernel.
    cudaLaunchAttribute attrs[1];
    attrs[0].id = cudaLaunchAttributeProgrammaticStreamSerialization;
    attrs[0].val.programmaticStreamSerializationAllowed = 1;

    cudaLaunchConfig_t cfg = {};
    cfg.gridDim  = dim3((NBATCH * M_LEN) / PPB, 1, 1);
    cfg.blockDim = dim3(256, 1, 1);
    cfg.dynamicSmemBytes = 0;
    cfg.stream = 0;
    cfg.attrs = attrs;
    cfg.numAttrs = 1;
    cudaLaunchKernelEx(&cfg, interp_kernel, om, t0, t1, (float*)d_out);
}